// round 1
// baseline (speedup 1.0000x reference)
#include <cuda_runtime.h>
#include <cstdint>

// Problem constants (fixed by the dataset; verified against in_sizes at launch)
#define MAX_NODES 100000
#define MAX_EDGES 1600000
#define ZD 128            // latent dim
#define ZD4 (ZD/4)        // float4 per node row = 32

// ---------------------------------------------------------------------------
// Scratch (no cudaMalloc allowed -> __device__ globals)
// ---------------------------------------------------------------------------
__device__ float g_proj_src[MAX_NODES];
__device__ float g_proj_dst[MAX_NODES];
__device__ float g_denom[MAX_NODES];
__device__ float g_agg[(size_t)MAX_NODES * ZD];   // 51.2 MB, fits in BSS

// SELU constants (match jax.nn.selu)
#define SELU_SCALE 1.0507009873554805f
#define SELU_SCALE_ALPHA 1.7580993408473766f   // scale * alpha

// ---------------------------------------------------------------------------
// K0: zero agg + denom
// ---------------------------------------------------------------------------
__global__ void init_kernel(int n_nodes) {
    int i = blockIdx.x * blockDim.x + threadIdx.x;
    int total4 = n_nodes * ZD4;               // float4 count for agg
    if (i < total4) {
        ((float4*)g_agg)[i] = make_float4(0.f, 0.f, 0.f, 0.f);
    }
    if (i < n_nodes) {
        g_denom[i] = 0.f;
    }
}

// ---------------------------------------------------------------------------
// K1: per-node projections  proj_src = z . w[:128], proj_dst = z . w[128:]
// One warp per node; each lane handles 4 dims, warp shfl reduction.
// ---------------------------------------------------------------------------
__global__ void proj_kernel(const float* __restrict__ z,
                            const float* __restrict__ w,
                            int n_nodes) {
    int gwarp = (blockIdx.x * blockDim.x + threadIdx.x) >> 5;
    int lane  = threadIdx.x & 31;
    if (gwarp >= n_nodes) return;

    float4 zv = ((const float4*)(z + (size_t)gwarp * ZD))[lane];
    float4 w1 = ((const float4*)w)[lane];        // first half of w
    float4 w2 = ((const float4*)w)[lane + 32];   // second half of w

    float s1 = zv.x * w1.x + zv.y * w1.y + zv.z * w1.z + zv.w * w1.w;
    float s2 = zv.x * w2.x + zv.y * w2.y + zv.z * w2.z + zv.w * w2.w;

    #pragma unroll
    for (int o = 16; o > 0; o >>= 1) {
        s1 += __shfl_xor_sync(0xFFFFFFFFu, s1, o);
        s2 += __shfl_xor_sync(0xFFFFFFFFu, s2, o);
    }
    if (lane == 0) {
        g_proj_src[gwarp] = s1;
        g_proj_dst[gwarp] = s2;
    }
}

// ---------------------------------------------------------------------------
// K2: fused edge pass. One warp per edge.
//   e   = selu(proj_src[src] + proj_dst[dst])
//   wgt = exp(e)                    (no segment-max needed: e in [-1.76, ~12])
//   denom[dst] += wgt               (scalar red, lane 0)
//   agg[dst][:] += wgt * z[src][:]  (red.global.add.v4.f32, one per lane)
// ---------------------------------------------------------------------------
__global__ void edge_kernel(const float* __restrict__ z,
                            const int*   __restrict__ src,
                            const int*   __restrict__ dst,
                            int n_edges) {
    int e    = (blockIdx.x * blockDim.x + threadIdx.x) >> 5;
    int lane = threadIdx.x & 31;
    if (e >= n_edges) return;

    int s = __ldg(src + e);
    int d = __ldg(dst + e);

    float x  = g_proj_src[s] + g_proj_dst[d];
    float ee = (x > 0.f) ? (SELU_SCALE * x)
                         : (SELU_SCALE_ALPHA * (__expf(x) - 1.0f));
    float wgt = __expf(ee);

    if (lane == 0) {
        atomicAdd(&g_denom[d], wgt);   // red.global.add.f32 (no return needed)
    }

    float4 zv = ((const float4*)(z + (size_t)s * ZD))[lane];
    float* ap = g_agg + (size_t)d * ZD + lane * 4;
    asm volatile("red.global.add.v4.f32 [%0], {%1, %2, %3, %4};"
                 :: "l"(ap),
                    "f"(wgt * zv.x), "f"(wgt * zv.y),
                    "f"(wgt * zv.z), "f"(wgt * zv.w)
                 : "memory");
}

// ---------------------------------------------------------------------------
// K3: finalize. out[n] = denom[n] > 0 ? agg[n]/denom[n] : z[n]
// One thread per float4.
// ---------------------------------------------------------------------------
__global__ void final_kernel(const float* __restrict__ z,
                             float* __restrict__ out,
                             int n_nodes) {
    int i = blockIdx.x * blockDim.x + threadIdx.x;
    int total4 = n_nodes * ZD4;
    if (i >= total4) return;

    int node = i >> 5;                 // ZD4 = 32 float4 per node
    float den = g_denom[node];
    float4 a  = ((const float4*)g_agg)[i];
    float4 zz = ((const float4*)z)[i];

    float4 r;
    if (den > 0.f) {
        float inv = 1.0f / den;
        r.x = a.x * inv; r.y = a.y * inv; r.z = a.z * inv; r.w = a.w * inv;
    } else {
        r = zz;
    }
    ((float4*)out)[i] = r;
}

// ---------------------------------------------------------------------------
// Harness entry point. Inputs (metadata order): z[f32 N*128], w[f32 256],
// src[i32 E], dst[i32 E]. Output: f32 N*128.
// ---------------------------------------------------------------------------
extern "C" void kernel_launch(void* const* d_in, const int* in_sizes, int n_in,
                              void* d_out, int out_size) {
    const float* z   = (const float*)d_in[0];
    const float* w   = (const float*)d_in[1];
    const int*   src = (const int*)  d_in[2];
    const int*   dst = (const int*)  d_in[3];
    float*       out = (float*)      d_out;

    int n_nodes = in_sizes[0] / ZD;
    int n_edges = in_sizes[2];
    if (n_nodes > MAX_NODES) n_nodes = MAX_NODES;   // scratch bound safety
    if (n_edges > MAX_EDGES) n_edges = MAX_EDGES;

    const int TPB = 256;

    // K0: zero scratch (covers n_nodes*32 float4 and n_nodes scalars)
    int init_elems = n_nodes * ZD4;
    init_kernel<<<(init_elems + TPB - 1) / TPB, TPB>>>(n_nodes);

    // K1: projections, one warp per node
    long long proj_threads = (long long)n_nodes * 32;
    proj_kernel<<<(int)((proj_threads + TPB - 1) / TPB), TPB>>>(z, w, n_nodes);

    // K2: fused edge pass, one warp per edge
    long long edge_threads = (long long)n_edges * 32;
    edge_kernel<<<(int)((edge_threads + TPB - 1) / TPB), TPB>>>(z, src, dst, n_edges);

    // K3: finalize
    final_kernel<<<(init_elems + TPB - 1) / TPB, TPB>>>(z, out, n_nodes);
}

// round 2
// speedup vs baseline: 2.2605x; 2.2605x over previous
#include <cuda_runtime.h>
#include <cstdint>

// Problem constants
#define MAX_NODES 100000
#define MAX_EDGES 1600000
#define ZD 128
#define ZD4 (ZD/4)           // 32 float4 per node row

#define SCAN_TPB 256
#define MAX_SCAN_BLOCKS ((MAX_NODES + SCAN_TPB - 1) / SCAN_TPB)   // 391

// ---------------------------------------------------------------------------
// Scratch (__device__ globals; no cudaMalloc allowed)
// ---------------------------------------------------------------------------
__device__ float g_proj_src[MAX_NODES];
__device__ float g_proj_dst[MAX_NODES];
__device__ int   g_counts[MAX_NODES];
__device__ int   g_offsets[MAX_NODES];
__device__ int   g_cursor[MAX_NODES];
__device__ int   g_blocksums[MAX_SCAN_BLOCKS];
__device__ int   g_blockoffs[MAX_SCAN_BLOCKS];
__device__ int2  g_edges[MAX_EDGES];     // .x = src node, .y = float bits of exp(selu(e))

// SELU constants (match jax.nn.selu)
#define SELU_SCALE 1.0507009873554805f
#define SELU_SCALE_ALPHA 1.7580993408473766f

// ---------------------------------------------------------------------------
// K0: zero per-node edge counts
// ---------------------------------------------------------------------------
__global__ void init_counts_kernel(int n_nodes) {
    int i = blockIdx.x * blockDim.x + threadIdx.x;
    if (i < n_nodes) g_counts[i] = 0;
}

// ---------------------------------------------------------------------------
// K1: per-node projections (warp per node)
// ---------------------------------------------------------------------------
__global__ void proj_kernel(const float* __restrict__ z,
                            const float* __restrict__ w,
                            int n_nodes) {
    int gwarp = (blockIdx.x * blockDim.x + threadIdx.x) >> 5;
    int lane  = threadIdx.x & 31;
    if (gwarp >= n_nodes) return;

    float4 zv = ((const float4*)(z + (size_t)gwarp * ZD))[lane];
    float4 w1 = ((const float4*)w)[lane];
    float4 w2 = ((const float4*)w)[lane + 32];

    float s1 = zv.x * w1.x + zv.y * w1.y + zv.z * w1.z + zv.w * w1.w;
    float s2 = zv.x * w2.x + zv.y * w2.y + zv.z * w2.z + zv.w * w2.w;

    #pragma unroll
    for (int o = 16; o > 0; o >>= 1) {
        s1 += __shfl_xor_sync(0xFFFFFFFFu, s1, o);
        s2 += __shfl_xor_sync(0xFFFFFFFFu, s2, o);
    }
    if (lane == 0) {
        g_proj_src[gwarp] = s1;
        g_proj_dst[gwarp] = s2;
    }
}

// ---------------------------------------------------------------------------
// K2: histogram of dst
// ---------------------------------------------------------------------------
__global__ void hist_kernel(const int* __restrict__ dst, int n_edges) {
    int e = blockIdx.x * blockDim.x + threadIdx.x;
    if (e < n_edges) atomicAdd(&g_counts[__ldg(dst + e)], 1);
}

// ---------------------------------------------------------------------------
// K3a/b/c: exclusive scan of counts -> offsets (3-phase block scan)
// ---------------------------------------------------------------------------
__global__ void scan1_kernel(int n) {
    __shared__ int sh[SCAN_TPB];
    int i = blockIdx.x * SCAN_TPB + threadIdx.x;
    int v = (i < n) ? g_counts[i] : 0;
    sh[threadIdx.x] = v;
    __syncthreads();
    #pragma unroll
    for (int o = 1; o < SCAN_TPB; o <<= 1) {
        int t = (threadIdx.x >= o) ? sh[threadIdx.x - o] : 0;
        __syncthreads();
        sh[threadIdx.x] += t;
        __syncthreads();
    }
    int inc = sh[threadIdx.x];
    if (i < n) g_offsets[i] = inc - v;                 // exclusive within block
    if (threadIdx.x == SCAN_TPB - 1) g_blocksums[blockIdx.x] = inc;
}

__global__ void scan2_kernel(int nblocks) {
    __shared__ int sh[512];
    int v = (threadIdx.x < nblocks) ? g_blocksums[threadIdx.x] : 0;
    sh[threadIdx.x] = v;
    __syncthreads();
    #pragma unroll
    for (int o = 1; o < 512; o <<= 1) {
        int t = (threadIdx.x >= o) ? sh[threadIdx.x - o] : 0;
        __syncthreads();
        sh[threadIdx.x] += t;
        __syncthreads();
    }
    if (threadIdx.x < nblocks) g_blockoffs[threadIdx.x] = sh[threadIdx.x] - v;
}

__global__ void scan3_kernel(int n) {
    int i = blockIdx.x * SCAN_TPB + threadIdx.x;
    if (i < n) {
        int o = g_offsets[i] + g_blockoffs[blockIdx.x];
        g_offsets[i] = o;
        g_cursor[i]  = o;
    }
}

// ---------------------------------------------------------------------------
// K4: scatter edges into CSR slots, computing the softmax weight on the way.
//     wgt = exp(selu(proj_src[s] + proj_dst[d]))  (no segment-max: selu output
//     bounded, exp cannot overflow fp32 here)
// ---------------------------------------------------------------------------
__global__ void scatter_kernel(const int* __restrict__ src,
                               const int* __restrict__ dst,
                               int n_edges) {
    int e = blockIdx.x * blockDim.x + threadIdx.x;
    if (e >= n_edges) return;

    int s = __ldg(src + e);
    int d = __ldg(dst + e);

    float x  = g_proj_src[s] + g_proj_dst[d];
    float ee = (x > 0.f) ? (SELU_SCALE * x)
                         : (SELU_SCALE_ALPHA * (__expf(x) - 1.0f));
    float wgt = __expf(ee);

    int pos = atomicAdd(&g_cursor[d], 1);
    g_edges[pos] = make_int2(s, __float_as_int(wgt));
}

// ---------------------------------------------------------------------------
// K5: aggregate. One warp per node; register accumulation; 2-way unroll
//     for memory-level parallelism. Writes the final normalized output.
// ---------------------------------------------------------------------------
__global__ void agg_kernel(const float* __restrict__ z,
                           float* __restrict__ out,
                           int n_nodes) {
    int node = (blockIdx.x * blockDim.x + threadIdx.x) >> 5;
    int lane = threadIdx.x & 31;
    if (node >= n_nodes) return;

    const float4* z4 = (const float4*)z;
    size_t orow = (size_t)node * ZD4 + lane;

    int cnt = g_counts[node];
    if (cnt == 0) {                        // untouched node: pass through z
        ((float4*)out)[orow] = __ldg(&z4[orow]);
        return;
    }
    int beg = g_offsets[node];

    float4 acc = make_float4(0.f, 0.f, 0.f, 0.f);
    float  den = 0.f;

    int j = 0;
    for (; j + 2 <= cnt; j += 2) {
        int2 e0 = g_edges[beg + j];
        int2 e1 = g_edges[beg + j + 1];
        float w0 = __int_as_float(e0.y);
        float w1 = __int_as_float(e1.y);
        float4 z0 = __ldg(&z4[(size_t)e0.x * ZD4 + lane]);
        float4 z1 = __ldg(&z4[(size_t)e1.x * ZD4 + lane]);
        den += w0 + w1;
        acc.x += w0 * z0.x + w1 * z1.x;
        acc.y += w0 * z0.y + w1 * z1.y;
        acc.z += w0 * z0.z + w1 * z1.z;
        acc.w += w0 * z0.w + w1 * z1.w;
    }
    if (j < cnt) {
        int2 e0 = g_edges[beg + j];
        float w0 = __int_as_float(e0.y);
        float4 z0 = __ldg(&z4[(size_t)e0.x * ZD4 + lane]);
        den += w0;
        acc.x += w0 * z0.x; acc.y += w0 * z0.y;
        acc.z += w0 * z0.z; acc.w += w0 * z0.w;
    }

    float inv = 1.0f / den;
    ((float4*)out)[orow] = make_float4(acc.x * inv, acc.y * inv,
                                       acc.z * inv, acc.w * inv);
}

// ---------------------------------------------------------------------------
// Entry point. Inputs: z[f32 N*128], w[f32 256], src[i32 E], dst[i32 E].
// ---------------------------------------------------------------------------
extern "C" void kernel_launch(void* const* d_in, const int* in_sizes, int n_in,
                              void* d_out, int out_size) {
    const float* z   = (const float*)d_in[0];
    const float* w   = (const float*)d_in[1];
    const int*   src = (const int*)  d_in[2];
    const int*   dst = (const int*)  d_in[3];
    float*       out = (float*)      d_out;

    int n_nodes = in_sizes[0] / ZD;
    int n_edges = in_sizes[2];
    if (n_nodes > MAX_NODES) n_nodes = MAX_NODES;
    if (n_edges > MAX_EDGES) n_edges = MAX_EDGES;

    const int TPB = 256;
    int scan_blocks = (n_nodes + SCAN_TPB - 1) / SCAN_TPB;

    init_counts_kernel<<<(n_nodes + TPB - 1) / TPB, TPB>>>(n_nodes);

    long long proj_threads = (long long)n_nodes * 32;
    proj_kernel<<<(int)((proj_threads + TPB - 1) / TPB), TPB>>>(z, w, n_nodes);

    hist_kernel<<<(n_edges + TPB - 1) / TPB, TPB>>>(dst, n_edges);

    scan1_kernel<<<scan_blocks, SCAN_TPB>>>(n_nodes);
    scan2_kernel<<<1, 512>>>(scan_blocks);
    scan3_kernel<<<scan_blocks, SCAN_TPB>>>(n_nodes);

    scatter_kernel<<<(n_edges + TPB - 1) / TPB, TPB>>>(src, dst, n_edges);

    long long agg_threads = (long long)n_nodes * 32;
    agg_kernel<<<(int)((agg_threads + TPB - 1) / TPB), TPB>>>(z, out, n_nodes);
}